// round 7
// baseline (speedup 1.0000x reference)
#include <cuda_runtime.h>

#define NN 50000
#define NE 800000
#define ETOT (NE + NN)   // 850000 edges incl. self loops
#define C 64

#define SCAN_BLK 1024
#define NSB ((NN + SCAN_BLK - 1) / SCAN_BLK)  // 49

// ---------------- scratch (no allocations allowed) ----------------
__device__ __align__(16) float d_z[NN * C];
__device__ __align__(16) float d_h[NN * C];
__device__ float d_es[NN];
__device__ float d_ed[NN];
__device__ float d_e[ETOT];          // per-edge logits in CSR order
__device__ int d_cnt[NN];
__device__ int d_off[NN + 1];
__device__ int d_pos[NN];
__device__ int d_bsum[NSB];
__device__ int d_csr_src[ETOT];
__device__ int d_csr_dst[ETOT];
__device__ int d_csr_eid[ETOT];

__device__ __forceinline__ void edge_sd(const int* __restrict__ ei,
                                        int i, int& s, int& d) {
    if (i < NE) { s = ei[i]; d = ei[NE + i]; }
    else        { s = i - NE; d = s; }
}

// ---------------- CSR build ----------------
__global__ void k_zero_cnt() {
    int t = blockIdx.x * blockDim.x + threadIdx.x;
    if (t < NN) d_cnt[t] = 0;
}

__global__ void k_hist(const int* __restrict__ ei) {
    int i = blockIdx.x * blockDim.x + threadIdx.x;
    if (i >= ETOT) return;
    int s, d; edge_sd(ei, i, s, d);
    atomicAdd(&d_cnt[d], 1);
}

__global__ void k_scan1() {
    int t = threadIdx.x, lane = t & 31, warp = t >> 5;
    int base = blockIdx.x * SCAN_BLK + t * 4;
    int c0 = (base + 0 < NN) ? d_cnt[base + 0] : 0;
    int c1 = (base + 1 < NN) ? d_cnt[base + 1] : 0;
    int c2 = (base + 2 < NN) ? d_cnt[base + 2] : 0;
    int c3 = (base + 3 < NN) ? d_cnt[base + 3] : 0;
    int s = c0 + c1 + c2 + c3;

    int inc = s;
#pragma unroll
    for (int o = 1; o < 32; o <<= 1) {
        int x = __shfl_up_sync(0xffffffffu, inc, o);
        if (lane >= o) inc += x;
    }
    __shared__ int wsum[8];
    if (lane == 31) wsum[warp] = inc;
    __syncthreads();
    if (t < 8) {
        int x = wsum[t];
        int ix = x;
#pragma unroll
        for (int o = 1; o < 8; o <<= 1) {
            int y = __shfl_up_sync(0xffu, ix, o);
            if (t >= o) ix += y;
        }
        wsum[t] = ix - x;
        if (t == 7) d_bsum[blockIdx.x] = ix;
    }
    __syncthreads();
    int excl = wsum[warp] + inc - s;
    if (base + 0 < NN) d_off[base + 0] = excl;
    if (base + 1 < NN) d_off[base + 1] = excl + c0;
    if (base + 2 < NN) d_off[base + 2] = excl + c0 + c1;
    if (base + 3 < NN) d_off[base + 3] = excl + c0 + c1 + c2;
}

__global__ void k_scan2() {
    int t = threadIdx.x;
    __shared__ int sh[64];
    sh[t] = (t < NSB) ? d_bsum[t] : 0;
    __syncthreads();
    int v = sh[t];
    int iv = v;
#pragma unroll
    for (int o = 1; o < 64; o <<= 1) {
        int x = (t >= o) ? sh[t - o] : 0;
        __syncthreads();
        sh[t] = iv = iv + x;
        __syncthreads();
    }
    if (t < NSB) d_bsum[t] = iv - v;
}

__global__ void k_scan3() {
    int t = threadIdx.x;
    int base = blockIdx.x * SCAN_BLK + t * 4;
    int bb = d_bsum[blockIdx.x];
#pragma unroll
    for (int k = 0; k < 4; k++) {
        int i = base + k;
        if (i < NN) { int o = d_off[i] + bb; d_off[i] = o; d_pos[i] = o; }
    }
    if (blockIdx.x == 0 && t == 0) d_off[NN] = ETOT;
}

__global__ void k_scatter(const int* __restrict__ ei) {
    int i = blockIdx.x * blockDim.x + threadIdx.x;
    if (i >= ETOT) return;
    int s, d; edge_sd(ei, i, s, d);
    int p = atomicAdd(&d_pos[d], 1);
    d_csr_src[p] = s;
    d_csr_dst[p] = d;
    d_csr_eid[p] = i;
}

// ---------------- per-layer compute ----------------
template <int CIN>
__global__ void __launch_bounds__(256) k_gemm(
        const float* __restrict__ hin,
        const float* __restrict__ W,
        const float* __restrict__ as_,
        const float* __restrict__ ad_) {
    const float* h = hin ? hin : d_h;
    int t  = threadIdx.x;
    int jg = t & 15;
    int nl = t >> 4;
    int node0 = blockIdx.x * 16;

    __shared__ __align__(16) float W_s[CIN * C];
    __shared__ __align__(16) float h_s[16][CIN + 4];

    {
        float4* Wd = (float4*)W_s;
        const float4* Ws = (const float4*)W;
#pragma unroll
        for (int i = t; i < CIN * C / 4; i += 256) Wd[i] = Ws[i];
        const float4* hs = (const float4*)h;
        for (int i = t; i < 16 * CIN / 4; i += 256) {
            int n = i / (CIN / 4), k4 = i % (CIN / 4);
            ((float4*)&h_s[n][0])[k4] = hs[(node0 + n) * (CIN / 4) + k4];
        }
    }
    __syncthreads();

    float4 acc = make_float4(0.f, 0.f, 0.f, 0.f);
    const float4* W4 = (const float4*)W_s;
#pragma unroll
    for (int k = 0; k < CIN; k++) {
        float hv = h_s[nl][k];
        float4 wv = W4[k * 16 + jg];
        acc.x = fmaf(hv, wv.x, acc.x);
        acc.y = fmaf(hv, wv.y, acc.y);
        acc.z = fmaf(hv, wv.z, acc.z);
        acc.w = fmaf(hv, wv.w, acc.w);
    }
    int node = node0 + nl;
    ((float4*)d_z)[node * 16 + jg] = acc;

    float4 av = ((const float4*)as_)[jg];
    float4 dv = ((const float4*)ad_)[jg];
    float ps = acc.x * av.x + acc.y * av.y + acc.z * av.z + acc.w * av.w;
    float pd = acc.x * dv.x + acc.y * dv.y + acc.z * dv.z + acc.w * dv.w;
#pragma unroll
    for (int o = 8; o; o >>= 1) {
        ps += __shfl_down_sync(0xffffffffu, ps, o, 16);
        pd += __shfl_down_sync(0xffffffffu, pd, o, 16);
    }
    if (jg == 0) { d_es[node] = ps; d_ed[node] = pd; }
}

// Per-edge logit in CSR order: v = leakyrelu_0.2(es[src] + ed[dst]).
// Edge-parallel: high MLP, coalesced write. Run once per layer.
__global__ void k_edge_v() {
    int i = blockIdx.x * blockDim.x + threadIdx.x;
    if (i >= ETOT) return;
    float v = d_es[d_csr_src[i]] + d_ed[d_csr_dst[i]];
    d_e[i] = v > 0.f ? v : 0.2f * v;
}

// Warp per dst node. d_e reads are contiguous per node range.
// Accumulate loop unrolled x2 with independent accumulators (MLP 4).
template <int WRITE_OUT>
__global__ void k_node(const float* __restrict__ b,
                       float* __restrict__ outh,
                       float* __restrict__ out_alpha) {
    int w = (blockIdx.x * blockDim.x + threadIdx.x) >> 5;
    if (w >= NN) return;
    int lane = threadIdx.x & 31;
    int beg = d_off[w], end = d_off[w + 1];

    float m = -1e30f;
    for (int e = beg + lane; e < end; e += 32) m = fmaxf(m, d_e[e]);
#pragma unroll
    for (int o = 16; o; o >>= 1) m = fmaxf(m, __shfl_xor_sync(0xffffffffu, m, o));

    float den = 0.f;
    for (int e = beg + lane; e < end; e += 32) den += __expf(d_e[e] - m);
#pragma unroll
    for (int o = 16; o; o >>= 1) den += __shfl_xor_sync(0xffffffffu, den, o);
    float inv = 1.f / (den + 1e-16f);

    float a0 = 0.f, a1 = 0.f, c0 = 0.f, c1 = 0.f;
    int e = beg;
    for (; e + 2 <= end; e += 2) {
        int   s0 = d_csr_src[e],     s1 = d_csr_src[e + 1];
        float l0 = __expf(d_e[e] - m) * inv;
        float l1 = __expf(d_e[e + 1] - m) * inv;
        a0 = fmaf(l0, d_z[s0 * C + lane], a0);
        a1 = fmaf(l0, d_z[s0 * C + 32 + lane], a1);
        c0 = fmaf(l1, d_z[s1 * C + lane], c0);
        c1 = fmaf(l1, d_z[s1 * C + 32 + lane], c1);
        if (WRITE_OUT && lane == 0) {
            out_alpha[d_csr_eid[e]] = l0;
            out_alpha[d_csr_eid[e + 1]] = l1;
        }
    }
    if (e < end) {
        int   s0 = d_csr_src[e];
        float l0 = __expf(d_e[e] - m) * inv;
        a0 = fmaf(l0, d_z[s0 * C + lane], a0);
        a1 = fmaf(l0, d_z[s0 * C + 32 + lane], a1);
        if (WRITE_OUT && lane == 0) out_alpha[d_csr_eid[e]] = l0;
    }
    a0 += c0; a1 += c1;

    float o0 = a0 + b[lane];      o0 = o0 > 0.f ? o0 : 0.01f * o0;
    float o1 = a1 + b[lane + 32]; o1 = o1 > 0.f ? o1 : 0.01f * o1;
    if (WRITE_OUT) { outh[w * C + lane] = o0; outh[w * C + 32 + lane] = o1; }
    else           { d_h[w * C + lane] = o0;  d_h[w * C + 32 + lane] = o1; }
}

// ei output region: [2, E+N] row-major, cast to float
__global__ void k_write_ei(const int* __restrict__ ei,
                           float* __restrict__ out) {
    int t = blockIdx.x * blockDim.x + threadIdx.x;
    if (t >= 2 * ETOT) return;
    int row = t / ETOT, k = t - row * ETOT;
    int v = (k < NE) ? ei[row * NE + k] : (k - NE);
    out[t] = (float)v;
}

extern "C" void kernel_launch(void* const* d_in, const int* in_sizes, int n_in,
                              void* d_out, int out_size) {
    const float* x  = (const float*)d_in[0];
    const int*   ei = (const int*)d_in[1];
    const float* W[3]   = {(const float*)d_in[2], (const float*)d_in[6],  (const float*)d_in[10]};
    const float* as_[3] = {(const float*)d_in[3], (const float*)d_in[7],  (const float*)d_in[11]};
    const float* ad_[3] = {(const float*)d_in[4], (const float*)d_in[8],  (const float*)d_in[12]};
    const float* b[3]   = {(const float*)d_in[5], (const float*)d_in[9],  (const float*)d_in[13]};

    float* out       = (float*)d_out;
    bool   tuple_out = (out_size > NN * C);
    float* out_ei    = tuple_out ? out + NN * C : nullptr;
    float* out_alpha = tuple_out ? out + NN * C + 2 * ETOT : nullptr;

    if (tuple_out)
        k_write_ei<<<(2 * ETOT + 255) / 256, 256>>>(ei, out_ei);

    k_zero_cnt<<<(NN + 255) / 256, 256>>>();
    k_hist<<<(ETOT + 255) / 256, 256>>>(ei);
    k_scan1<<<NSB, 256>>>();
    k_scan2<<<1, 64>>>();
    k_scan3<<<NSB, 256>>>();
    k_scatter<<<(ETOT + 255) / 256, 256>>>(ei);

    for (int l = 0; l < 3; l++) {
        if (l == 0) k_gemm<128><<<NN / 16, 256>>>(x, W[0], as_[0], ad_[0]);
        else        k_gemm<64><<<NN / 16, 256>>>(nullptr, W[l], as_[l], ad_[l]);
        k_edge_v<<<(ETOT + 255) / 256, 256>>>();
        if (l == 2) k_node<1><<<(NN * 32 + 255) / 256, 256>>>(b[l], out, out_alpha);
        else        k_node<0><<<(NN * 32 + 255) / 256, 256>>>(b[l], nullptr, nullptr);
    }
}